// round 3
// baseline (speedup 1.0000x reference)
#include <cuda_runtime.h>
#include <cstdint>

#define E_ 11
#define B_ 1024
#define D_ 1536
#define H_ 3072
#define C_ 5242

#define BM 128
#define BN 128
#define BK 32
#define NTHREADS 128          // 4 warps: 2 (M) x 2 (N), warp tile 64x64
#define MT 4                  // m-tiles of 128 rows covered per bin (safety >128)
#define SAS 36                // A smem stride (floats): conflict-free fragments
#define SBS 136               // B smem stride (floats): conflict-free fragments
#define SA_ELEMS (BM * SAS)   // 4608
#define SB_ELEMS (BK * SBS)   // 4352
#define STAGE_ELEMS (SA_ELEMS + SB_ELEMS)
#define SMEM_BYTES (2 * STAGE_ELEMS * 4)   // 71680 B

// ---- scratch (device globals: no allocations allowed) ----
__device__ int   g_cnt[E_];
__device__ int   g_idx[E_ * B_];
__device__ float g_h1[(size_t)B_ * H_];
__device__ float g_h2[(size_t)B_ * H_];

// ---------------------------------------------------------------------------
__global__ void route_kernel(const float* __restrict__ mf) {
    int tid = threadIdx.x;
    if (tid < E_) g_cnt[tid] = 0;
    __syncthreads();
    float t = 1.0f - mf[tid];
    float q = t / 0.1f;               // IEEE div, matches XLA lowering
    int bin = (int)q;                 // trunc toward zero == astype(int32)
    bin = max(0, min(E_ - 1, bin));
    int pos = atomicAdd(&g_cnt[bin], 1);
    g_idx[bin * B_ + pos] = tid;
}

// ---- PTX helpers ----------------------------------------------------------
__device__ __forceinline__ void cp_async16(uint32_t s, const float* g) {
    asm volatile("cp.async.cg.shared.global [%0], [%1], 16;\n" :: "r"(s), "l"(g));
}
__device__ __forceinline__ void cp_async8(uint32_t s, const float* g, int bytes) {
    asm volatile("cp.async.ca.shared.global [%0], [%1], 8, %2;\n"
                 :: "r"(s), "l"(g), "r"(bytes));
}
__device__ __forceinline__ void cp_commit() {
    asm volatile("cp.async.commit_group;\n" ::: "memory");
}
template <int N>
__device__ __forceinline__ void cp_wait() {
    asm volatile("cp.async.wait_group %0;\n" :: "n"(N) : "memory");
}
__device__ __forceinline__ void mma_tf32(float c[4], const uint32_t a[4],
                                         const uint32_t b[2]) {
    asm volatile(
        "mma.sync.aligned.m16n8k8.row.col.f32.tf32.tf32.f32 "
        "{%0,%1,%2,%3}, {%4,%5,%6,%7}, {%8,%9}, {%0,%1,%2,%3};\n"
        : "+f"(c[0]), "+f"(c[1]), "+f"(c[2]), "+f"(c[3])
        : "r"(a[0]), "r"(a[1]), "r"(a[2]), "r"(a[3]), "r"(b[0]), "r"(b[1]));
}
__device__ __forceinline__ float gelu_exact(float x) {
    return 0.5f * x * (1.0f + erff(x * 0.70710678118654752f));
}

// ---------------------------------------------------------------------------
// Per-bin gather GEMM, warp tile 64x64, CTA tile 128x128, tf32 mma.sync.
// grid = (ceil(N/BN), MT, E); blocks beyond this bin's row count exit early.
// ---------------------------------------------------------------------------
template <bool DO_GELU, bool ALIGN16>
__global__ void __launch_bounds__(NTHREADS, 2)
expert_gemm(const float* __restrict__ A, int lda,
            const float* __restrict__ W, const float* __restrict__ bias,
            float* __restrict__ Cout, int ldc, int K, int N)
{
    const int e = blockIdx.z;
    const int cnt = g_cnt[e];
    const int mtile = blockIdx.y;
    if (mtile * BM >= cnt) return;
    const int n0 = blockIdx.x * BN;

    const int* idxE = g_idx + e * B_;
    const float* We = W + (size_t)e * K * N;
    const float* be = bias + (size_t)e * N;

    extern __shared__ float smem[];
    const uint32_t s_base = (uint32_t)__cvta_generic_to_shared(smem);

    const int tid = threadIdx.x;

    // ---- A gather: thread = one gathered row, 8x cp16 over 32 k-floats ----
    int gm = mtile * BM + tid;
    int gmc = gm < cnt ? gm : cnt - 1;
    const float* a_src = A + (size_t)idxE[gmc] * lda;
    const uint32_t a_dst = s_base + (uint32_t)(tid * SAS * 4);

    // ---- B: 4 threads per k-row, 32 n-floats each ----
    const int b_row = tid >> 2;                 // 0..31
    const int b_col = (tid & 3) * 32;           // 0,32,64,96
    const float* b_src = We + (size_t)b_row * N + n0 + b_col;
    const uint32_t b_dst = s_base + (uint32_t)((SA_ELEMS + b_row * SBS + b_col) * 4);

    const int KT = K / BK;

    auto issue = [&](int t) {
        const uint32_t soff = (uint32_t)((t & 1) * STAGE_ELEMS * 4);
        const size_t k0 = (size_t)t * BK;
        const float* as = a_src + k0;
#pragma unroll
        for (int j = 0; j < 8; j++) cp_async16(a_dst + soff + j * 16, as + 4 * j);
        const float* bs = b_src + k0 * N;
        if (ALIGN16) {
#pragma unroll
            for (int j = 0; j < 8; j++) cp_async16(b_dst + soff + j * 16, bs + 4 * j);
        } else {
#pragma unroll
            for (int j = 0; j < 16; j++) {
                int gn = n0 + b_col + 2 * j;
                int bytes = (gn < N) ? 8 : 0;
                const float* p = bs + 2 * j;
                if (gn >= N) p = bs;            // keep address valid; zfilled
                cp_async8(b_dst + soff + j * 8, p, bytes);
            }
        }
        cp_commit();
    };
    issue(0);

    const int lane = tid & 31;
    const int warp = tid >> 5;
    const int wm = (warp & 1) * 64;   // 2 warps along M
    const int wn = (warp >> 1) * 64;  // 2 warps along N
    const int g  = lane >> 2;
    const int tg = lane & 3;

    float acc[4][8][4];
#pragma unroll
    for (int mi = 0; mi < 4; mi++)
#pragma unroll
        for (int ni = 0; ni < 8; ni++)
#pragma unroll
            for (int k = 0; k < 4; k++) acc[mi][ni][k] = 0.f;

    for (int t = 0; t < KT; t++) {
        if (t + 1 < KT) { issue(t + 1); cp_wait<1>(); }
        else           { cp_wait<0>(); }
        __syncthreads();
        const float* cA = smem + (t & 1) * STAGE_ELEMS;
        const float* cB = cA + SA_ELEMS;
#pragma unroll
        for (int ks = 0; ks < 4; ks++) {
            uint32_t af[4][4], bf[8][2];
            const int kc = ks * 8 + tg;
#pragma unroll
            for (int mi = 0; mi < 4; mi++) {
                const int row = wm + mi * 16 + g;
                af[mi][0] = __float_as_uint(cA[row * SAS + kc]);
                af[mi][1] = __float_as_uint(cA[(row + 8) * SAS + kc]);
                af[mi][2] = __float_as_uint(cA[row * SAS + kc + 4]);
                af[mi][3] = __float_as_uint(cA[(row + 8) * SAS + kc + 4]);
            }
#pragma unroll
            for (int ni = 0; ni < 8; ni++) {
                const int coln = wn + ni * 8 + g;
                bf[ni][0] = __float_as_uint(cB[kc * SBS + coln]);
                bf[ni][1] = __float_as_uint(cB[(kc + 4) * SBS + coln]);
            }
#pragma unroll
            for (int mi = 0; mi < 4; mi++)
#pragma unroll
                for (int ni = 0; ni < 8; ni++)
                    mma_tf32(acc[mi][ni], af[mi], bf[ni]);
        }
        __syncthreads();
    }

    // ---- epilogue: bias (+gelu), scatter to original rows ----
#pragma unroll
    for (int mi = 0; mi < 4; mi++) {
#pragma unroll
        for (int half = 0; half < 2; half++) {
            const int m = wm + mi * 16 + g + half * 8;
            const int gmm = mtile * BM + m;
            if (gmm >= cnt) continue;
            float* orow = Cout + (size_t)idxE[gmm] * ldc;
#pragma unroll
            for (int ni = 0; ni < 8; ni++) {
                const int gn = n0 + wn + ni * 8 + tg * 2;
                float v0 = acc[mi][ni][half * 2 + 0];
                float v1 = acc[mi][ni][half * 2 + 1];
                if (gn + 1 < N) {
                    float r0 = v0 + be[gn];
                    float r1 = v1 + be[gn + 1];
                    if (DO_GELU) { r0 = gelu_exact(r0); r1 = gelu_exact(r1); }
                    *reinterpret_cast<float2*>(orow + gn) = make_float2(r0, r1);
                } else if (gn < N) {
                    float r0 = v0 + be[gn];
                    if (DO_GELU) r0 = gelu_exact(r0);
                    orow[gn] = r0;
                }
            }
        }
    }
}

// ---------------------------------------------------------------------------
__global__ void logsoftmax_kernel(float* __restrict__ out) {
    const int b = blockIdx.x;
    float* row = out + (size_t)b * C_;
    __shared__ float sred[256];
    const int tid = threadIdx.x;

    float lmax = -3.4e38f;
    for (int i = tid; i < C_; i += 256) lmax = fmaxf(lmax, row[i]);
    sred[tid] = lmax;
    __syncthreads();
    for (int s = 128; s > 0; s >>= 1) {
        if (tid < s) sred[tid] = fmaxf(sred[tid], sred[tid + s]);
        __syncthreads();
    }
    const float mx = sred[0];
    __syncthreads();

    float lsum = 0.f;
    for (int i = tid; i < C_; i += 256) lsum += expf(row[i] - mx);
    sred[tid] = lsum;
    __syncthreads();
    for (int s = 128; s > 0; s >>= 1) {
        if (tid < s) sred[tid] += sred[tid + s];
        __syncthreads();
    }
    const float lse = mx + logf(sred[0]);

    for (int i = tid; i < C_; i += 256) row[i] = row[i] - lse;
}

// ---------------------------------------------------------------------------
extern "C" void kernel_launch(void* const* d_in, const int* in_sizes, int n_in,
                              void* d_out, int out_size)
{
    const float* x  = (const float*)d_in[0];
    const float* mf = (const float*)d_in[1];
    const float* W1 = (const float*)d_in[2];
    const float* b1 = (const float*)d_in[3];
    const float* W2 = (const float*)d_in[4];
    const float* b2 = (const float*)d_in[5];
    const float* W3 = (const float*)d_in[6];
    const float* b3 = (const float*)d_in[7];
    float* out = (float*)d_out;

    void *h1p = nullptr, *h2p = nullptr;
    cudaGetSymbolAddress(&h1p, g_h1);
    cudaGetSymbolAddress(&h2p, g_h2);

    cudaFuncSetAttribute(expert_gemm<true, true>,
                         cudaFuncAttributeMaxDynamicSharedMemorySize, SMEM_BYTES);
    cudaFuncSetAttribute(expert_gemm<false, false>,
                         cudaFuncAttributeMaxDynamicSharedMemorySize, SMEM_BYTES);

    route_kernel<<<1, B_>>>(mf);

    // L1: [cnt,1536] @ [1536,3072] -> gelu -> h1   (N=3072: rows 16B-aligned)
    expert_gemm<true, true><<<dim3(H_ / BN, MT, E_), NTHREADS, SMEM_BYTES>>>(
        x, D_, W1, b1, (float*)h1p, H_, D_, H_);
    // L2: [cnt,3072] @ [3072,3072] -> gelu -> h2
    expert_gemm<true, true><<<dim3(H_ / BN, MT, E_), NTHREADS, SMEM_BYTES>>>(
        (float*)h1p, H_, W2, b2, (float*)h2p, H_, H_, H_);
    // L3: [cnt,3072] @ [3072,5242] + b3 -> preds   (N=5242: only 8B-aligned)
    expert_gemm<false, false><<<dim3((C_ + BN - 1) / BN, MT, E_), NTHREADS, SMEM_BYTES>>>(
        (float*)h2p, H_, W3, b3, out, C_, H_, C_);
    logsoftmax_kernel<<<B_, 256>>>(out);
}

// round 4
// speedup vs baseline: 1.9955x; 1.9955x over previous
#include <cuda_runtime.h>
#include <cuda_fp16.h>
#include <cstdint>

#define E_ 11
#define B_ 1024
#define D_ 1536
#define H_ 3072
#define C_ 5242

#define BM 128
#define BN 128
#define BK 16
#define NTHREADS 256
#define MT 2
#define SAS 24                 // A smem stride (halves): LDSM conflict-free
#define SBS 136                // B smem stride (halves): LDSM conflict-free
#define SA_H (BM * SAS)        // 3072 halves
#define SB_H (BK * SBS)        // 2176 halves
#define STAGE_H (SA_H + SB_H)  // 5248 halves = 10496 B/stage

// ---- scratch (device globals: no allocations allowed) ----
__device__ int    g_cnt[E_];
__device__ int    g_idx[E_ * B_];
__device__ __half g_h1[(size_t)B_ * H_];
__device__ __half g_h2[(size_t)B_ * H_];

// ---------------------------------------------------------------------------
__global__ void route_kernel(const float* __restrict__ mf) {
    int tid = threadIdx.x;
    if (tid < E_) g_cnt[tid] = 0;
    __syncthreads();
    float t = 1.0f - mf[tid];
    float q = t / 0.1f;               // IEEE div, matches XLA lowering
    int bin = (int)q;                 // trunc toward zero == astype(int32)
    bin = max(0, min(E_ - 1, bin));
    int pos = atomicAdd(&g_cnt[bin], 1);
    g_idx[bin * B_ + pos] = tid;
}

// ---- PTX helpers ----------------------------------------------------------
__device__ __forceinline__ void ldsm4(uint32_t r[4], uint32_t addr) {
    asm volatile("ldmatrix.sync.aligned.m8n8.x4.shared.b16 {%0,%1,%2,%3}, [%4];"
                 : "=r"(r[0]), "=r"(r[1]), "=r"(r[2]), "=r"(r[3]) : "r"(addr));
}
__device__ __forceinline__ void ldsm4t(uint32_t r[4], uint32_t addr) {
    asm volatile("ldmatrix.sync.aligned.m8n8.x4.trans.shared.b16 {%0,%1,%2,%3}, [%4];"
                 : "=r"(r[0]), "=r"(r[1]), "=r"(r[2]), "=r"(r[3]) : "r"(addr));
}
__device__ __forceinline__ void mma_f16(float c[4], const uint32_t a[4],
                                        const uint32_t b0, const uint32_t b1) {
    asm volatile(
        "mma.sync.aligned.m16n8k16.row.col.f32.f16.f16.f32 "
        "{%0,%1,%2,%3}, {%4,%5,%6,%7}, {%8,%9}, {%0,%1,%2,%3};\n"
        : "+f"(c[0]), "+f"(c[1]), "+f"(c[2]), "+f"(c[3])
        : "r"(a[0]), "r"(a[1]), "r"(a[2]), "r"(a[3]), "r"(b0), "r"(b1));
}
__device__ __forceinline__ void sts128(uint32_t addr, const uint32_t v[4]) {
    asm volatile("st.shared.v4.b32 [%0], {%1,%2,%3,%4};\n"
                 :: "r"(addr), "r"(v[0]), "r"(v[1]), "r"(v[2]), "r"(v[3]));
}
__device__ __forceinline__ uint32_t pack2(float x, float y) {
    __half2 h = __float22half2_rn(make_float2(x, y));
    return *reinterpret_cast<uint32_t*>(&h);
}
__device__ __forceinline__ float gelu_exact(float x) {
    return 0.5f * x * (1.0f + erff(x * 0.70710678118654752f));
}

// ---------------------------------------------------------------------------
// Per-bin gather GEMM: fp16 mma.sync (fp32 accum), ldmatrix fragments.
// CTA 128x128, 8 warps (2Mx4N, warp tile 64x32), BK=16, reg-double-buffered.
// ---------------------------------------------------------------------------
template <bool DO_GELU, bool A_HALF, bool OUT_HALF, bool ALIGN16>
__global__ void __launch_bounds__(NTHREADS, 2)
expert_gemm(const void* __restrict__ Av, int lda,
            const float* __restrict__ W, const float* __restrict__ bias,
            void* __restrict__ Coutv, int ldc, int K, int N)
{
    const int e = blockIdx.z;
    const int cnt = g_cnt[e];
    const int mtile = blockIdx.y;
    if (mtile * BM >= cnt) return;
    const int n0 = blockIdx.x * BN;

    const int* idxE = g_idx + e * B_;
    const float* We = W + (size_t)e * K * N;
    const float* be = bias + (size_t)e * N;

    __shared__ __half smem[2 * STAGE_H];
    const uint32_t s_u32 = (uint32_t)__cvta_generic_to_shared(smem);

    const int tid = threadIdx.x;
    const int lane = tid & 31;
    const int warp = tid >> 5;

    // ---- A loader: row rA = tid>>1, k-offset 8*(tid&1), 8 halves -> STS.128
    const int rA = tid >> 1;
    const int ha = tid & 1;
    int gm = mtile * BM + rA;
    int gmc = gm < cnt ? gm : cnt - 1;
    const int arow = idxE[gmc];
    const float*  a_f = (const float*)Av  + (size_t)arow * lda + 8 * ha;
    const __half* a_h = (const __half*)Av + (size_t)arow * lda + 8 * ha;
    const uint32_t a_sts = s_u32 + (uint32_t)((rA * SAS + 8 * ha) * 2);

    // ---- B loader: k-row kB = tid>>4, n-chunk (tid&15)*8, 8 floats -> STS.128
    const int kB = tid >> 4;
    const int nch = (tid & 15) * 8;
    const float* b_src = We + (size_t)kB * N + n0 + nch;
    const uint32_t b_sts = s_u32 + (uint32_t)((SA_H + kB * SBS + nch) * 2);

    const int KT = K / BK;
    uint32_t bufA[4], bufB[4];

    auto load_g = [&](int t) {
        // A
        if (A_HALF) {
            uint4 v = *reinterpret_cast<const uint4*>(a_h + (size_t)t * BK);
            bufA[0] = v.x; bufA[1] = v.y; bufA[2] = v.z; bufA[3] = v.w;
        } else {
            float4 v0 = *reinterpret_cast<const float4*>(a_f + (size_t)t * BK);
            float4 v1 = *reinterpret_cast<const float4*>(a_f + (size_t)t * BK + 4);
            bufA[0] = pack2(v0.x, v0.y); bufA[1] = pack2(v0.z, v0.w);
            bufA[2] = pack2(v1.x, v1.y); bufA[3] = pack2(v1.z, v1.w);
        }
        // B
        const float* bs = b_src + (size_t)t * BK * N;
        if (ALIGN16) {
            float4 v0 = *reinterpret_cast<const float4*>(bs);
            float4 v1 = *reinterpret_cast<const float4*>(bs + 4);
            bufB[0] = pack2(v0.x, v0.y); bufB[1] = pack2(v0.z, v0.w);
            bufB[2] = pack2(v1.x, v1.y); bufB[3] = pack2(v1.z, v1.w);
        } else {
#pragma unroll
            for (int j = 0; j < 4; j++) {
                int gn = n0 + nch + 2 * j;
                if (gn < N) {
                    float2 v = *reinterpret_cast<const float2*>(bs + 2 * j);
                    bufB[j] = pack2(v.x, v.y);
                } else {
                    bufB[j] = 0u;
                }
            }
        }
    };
    auto do_sts = [&](int stage) {
        const uint32_t off = (uint32_t)(stage * STAGE_H * 2);
        sts128(a_sts + off, bufA);
        sts128(b_sts + off, bufB);
    };

    // warp tiling: 2 warps along M (64), 4 along N (32)
    const int wm = (warp & 1) * 64;
    const int wn = (warp >> 1) * 32;
    const int g  = lane >> 2;
    const int tg = lane & 3;

    // ldmatrix source addresses (per-warp, stage-relative)
    const int a_ld_row = wm + (lane & 15);
    const int a_ld_col = (lane >> 4) * 8;
    const uint32_t a_ld = s_u32 + (uint32_t)((a_ld_row * SAS + a_ld_col) * 2);
    const int b_ld_k = lane & 15;
    const int b_ld_n = wn + (lane >> 4) * 8;
    const uint32_t b_ld = s_u32 + (uint32_t)((SA_H + b_ld_k * SBS + b_ld_n) * 2);

    float acc[4][4][4];
#pragma unroll
    for (int mi = 0; mi < 4; mi++)
#pragma unroll
        for (int ni = 0; ni < 4; ni++)
#pragma unroll
            for (int k = 0; k < 4; k++) acc[mi][ni][k] = 0.f;

    load_g(0);
    do_sts(0);

    for (int t = 0; t < KT; t++) {
        __syncthreads();
        if (t + 1 < KT) load_g(t + 1);

        const uint32_t soff = (uint32_t)((t & 1) * STAGE_H * 2);
        uint32_t bf[8];
        ldsm4t(bf,     b_ld + soff);            // ni 0,1 (n..n+15)
        ldsm4t(bf + 4, b_ld + soff + 32);       // ni 2,3 (n+16..n+31)
#pragma unroll
        for (int mi = 0; mi < 4; mi++) {
            uint32_t af[4];
            ldsm4(af, a_ld + soff + (uint32_t)(mi * 16 * SAS * 2));
            // bf tile order per ldsm4t: [k0-7,n][k8-15,n][k0-7,n+8][k8-15,n+8]
            mma_f16(acc[mi][0], af, bf[0], bf[1]);
            mma_f16(acc[mi][1], af, bf[2], bf[3]);
            mma_f16(acc[mi][2], af, bf[4], bf[5]);
            mma_f16(acc[mi][3], af, bf[6], bf[7]);
        }

        if (t + 1 < KT) do_sts((t + 1) & 1);
    }

    // ---- epilogue: bias (+gelu), scatter to original sample rows ----
#pragma unroll
    for (int mi = 0; mi < 4; mi++) {
#pragma unroll
        for (int half = 0; half < 2; half++) {
            const int m = wm + mi * 16 + g + half * 8;
            const int gmm = mtile * BM + m;
            if (gmm >= cnt) continue;
            const int orow = idxE[gmm];
#pragma unroll
            for (int ni = 0; ni < 4; ni++) {
                const int gn = n0 + wn + ni * 8 + tg * 2;
                float v0 = acc[mi][ni][half * 2 + 0];
                float v1 = acc[mi][ni][half * 2 + 1];
                if (OUT_HALF) {
                    // L1/L2: N multiple of 128, no bounds needed
                    float r0 = v0 + be[gn];
                    float r1 = v1 + be[gn + 1];
                    if (DO_GELU) { r0 = gelu_exact(r0); r1 = gelu_exact(r1); }
                    __half2 hv = __float22half2_rn(make_float2(r0, r1));
                    *reinterpret_cast<__half2*>((__half*)Coutv + (size_t)orow * ldc + gn) = hv;
                } else {
                    float* op = (float*)Coutv + (size_t)orow * ldc;
                    if (gn + 1 < N) {
                        float r0 = v0 + be[gn];
                        float r1 = v1 + be[gn + 1];
                        if (DO_GELU) { r0 = gelu_exact(r0); r1 = gelu_exact(r1); }
                        *reinterpret_cast<float2*>(op + gn) = make_float2(r0, r1);
                    } else if (gn < N) {
                        float r0 = v0 + be[gn];
                        if (DO_GELU) r0 = gelu_exact(r0);
                        op[gn] = r0;
                    }
                }
            }
        }
    }
}

// ---------------------------------------------------------------------------
__global__ void logsoftmax_kernel(float* __restrict__ out) {
    const int b = blockIdx.x;
    float* row = out + (size_t)b * C_;
    __shared__ float sred[256];
    const int tid = threadIdx.x;

    float lmax = -3.4e38f;
    for (int i = tid; i < C_; i += 256) lmax = fmaxf(lmax, row[i]);
    sred[tid] = lmax;
    __syncthreads();
    for (int s = 128; s > 0; s >>= 1) {
        if (tid < s) sred[tid] = fmaxf(sred[tid], sred[tid + s]);
        __syncthreads();
    }
    const float mx = sred[0];
    __syncthreads();

    float lsum = 0.f;
    for (int i = tid; i < C_; i += 256) lsum += expf(row[i] - mx);
    sred[tid] = lsum;
    __syncthreads();
    for (int s = 128; s > 0; s >>= 1) {
        if (tid < s) sred[tid] += sred[tid + s];
        __syncthreads();
    }
    const float lse = mx + logf(sred[0]);

    for (int i = tid; i < C_; i += 256) row[i] = row[i] - lse;
}

// ---------------------------------------------------------------------------
extern "C" void kernel_launch(void* const* d_in, const int* in_sizes, int n_in,
                              void* d_out, int out_size)
{
    const float* x  = (const float*)d_in[0];
    const float* mf = (const float*)d_in[1];
    const float* W1 = (const float*)d_in[2];
    const float* b1 = (const float*)d_in[3];
    const float* W2 = (const float*)d_in[4];
    const float* b2 = (const float*)d_in[5];
    const float* W3 = (const float*)d_in[6];
    const float* b3 = (const float*)d_in[7];
    float* out = (float*)d_out;

    void *h1p = nullptr, *h2p = nullptr;
    cudaGetSymbolAddress(&h1p, g_h1);
    cudaGetSymbolAddress(&h2p, g_h2);

    route_kernel<<<1, B_>>>(mf);

    // L1: x fp32 [cnt,1536] @ W1 -> gelu -> h1 (fp16)
    expert_gemm<true, false, true, true>
        <<<dim3(H_ / BN, MT, E_), NTHREADS>>>(x, D_, W1, b1, h1p, H_, D_, H_);
    // L2: h1 fp16 [cnt,3072] @ W2 -> gelu -> h2 (fp16)
    expert_gemm<true, true, true, true>
        <<<dim3(H_ / BN, MT, E_), NTHREADS>>>(h1p, H_, W2, b2, h2p, H_, H_, H_);
    // L3: h2 fp16 [cnt,3072] @ W3 + b3 -> preds (fp32, 8B-aligned rows)
    expert_gemm<false, true, false, false>
        <<<dim3((C_ + BN - 1) / BN, MT, E_), NTHREADS>>>(h2p, H_, W3, b3, out, C_, H_, C_);
    logsoftmax_kernel<<<B_, 256>>>(out);
}

// round 5
// speedup vs baseline: 2.0243x; 1.0144x over previous
#include <cuda_runtime.h>
#include <cuda_fp16.h>
#include <cstdint>

#define E_ 11
#define B_ 1024
#define D_ 1536
#define H_ 3072
#define C_ 5242

#define BM 128
#define BN 128
#define BK 16
#define NTHREADS 256
#define MT 2
#define SAS 24                 // A smem stride (halves): LDSM conflict-free
#define SBS 136                // B smem stride (halves): LDSM conflict-free
#define SA_H (BM * SAS)        // 3072 halves
#define SB_H (BK * SBS)        // 2176 halves
#define STAGE_H (SA_H + SB_H)  // 5248 halves = 10496 B/stage

// ---- scratch (device globals: no allocations allowed) ----
__device__ int    g_cnt[E_];
__device__ int    g_idx[E_ * B_];
__device__ __half g_h1[(size_t)B_ * H_];
__device__ __half g_h2[(size_t)B_ * H_];

// ---------------------------------------------------------------------------
__global__ void route_kernel(const float* __restrict__ mf) {
    int tid = threadIdx.x;
    if (tid < E_) g_cnt[tid] = 0;
    __syncthreads();
    float t = 1.0f - mf[tid];
    float q = t / 0.1f;               // IEEE div, matches XLA lowering
    int bin = (int)q;                 // trunc toward zero == astype(int32)
    bin = max(0, min(E_ - 1, bin));
    int pos = atomicAdd(&g_cnt[bin], 1);
    g_idx[bin * B_ + pos] = tid;
}

// ---- PTX helpers ----------------------------------------------------------
__device__ __forceinline__ void ldsm4(uint32_t r[4], uint32_t addr) {
    asm volatile("ldmatrix.sync.aligned.m8n8.x4.shared.b16 {%0,%1,%2,%3}, [%4];"
                 : "=r"(r[0]), "=r"(r[1]), "=r"(r[2]), "=r"(r[3]) : "r"(addr));
}
__device__ __forceinline__ void ldsm4t(uint32_t r[4], uint32_t addr) {
    asm volatile("ldmatrix.sync.aligned.m8n8.x4.trans.shared.b16 {%0,%1,%2,%3}, [%4];"
                 : "=r"(r[0]), "=r"(r[1]), "=r"(r[2]), "=r"(r[3]) : "r"(addr));
}
__device__ __forceinline__ void mma_f16(float c[4], const uint32_t a[4],
                                        const uint32_t b0, const uint32_t b1) {
    asm volatile(
        "mma.sync.aligned.m16n8k16.row.col.f32.f16.f16.f32 "
        "{%0,%1,%2,%3}, {%4,%5,%6,%7}, {%8,%9}, {%0,%1,%2,%3};\n"
        : "+f"(c[0]), "+f"(c[1]), "+f"(c[2]), "+f"(c[3])
        : "r"(a[0]), "r"(a[1]), "r"(a[2]), "r"(a[3]), "r"(b0), "r"(b1));
}
__device__ __forceinline__ void sts128(uint32_t addr, const uint32_t v[4]) {
    asm volatile("st.shared.v4.b32 [%0], {%1,%2,%3,%4};\n"
                 :: "r"(addr), "r"(v[0]), "r"(v[1]), "r"(v[2]), "r"(v[3]));
}
__device__ __forceinline__ uint32_t pack2(float x, float y) {
    __half2 h = __float22half2_rn(make_float2(x, y));
    return *reinterpret_cast<uint32_t*>(&h);
}
__device__ __forceinline__ float gelu_exact(float x) {
    return 0.5f * x * (1.0f + erff(x * 0.70710678118654752f));
}

// ---------------------------------------------------------------------------
// Per-bin gather GEMM: fp16 mma.sync (fp32 accum), ldmatrix fragments.
// CTA 128x128, 8 warps (2Mx4N, warp tile 64x32), BK=16, reg-double-buffered.
// ---------------------------------------------------------------------------
template <bool DO_GELU, bool A_HALF, bool OUT_HALF, bool ALIGN16>
__global__ void __launch_bounds__(NTHREADS, 2)
expert_gemm(const void* __restrict__ Av, int lda,
            const float* __restrict__ W, const float* __restrict__ bias,
            void* __restrict__ Coutv, int ldc, int K, int N)
{
    const int e = blockIdx.z;
    const int cnt = g_cnt[e];
    const int mtile = blockIdx.y;
    if (mtile * BM >= cnt) return;
    const int n0 = blockIdx.x * BN;

    const int* idxE = g_idx + e * B_;
    const float* We = W + (size_t)e * K * N;
    const float* be = bias + (size_t)e * N;

    __shared__ __half smem[2 * STAGE_H];
    const uint32_t s_u32 = (uint32_t)__cvta_generic_to_shared(smem);

    const int tid = threadIdx.x;
    const int lane = tid & 31;
    const int warp = tid >> 5;

    // ---- A loader: row rA = tid>>1, k-offset 8*(tid&1), 8 halves -> STS.128
    const int rA = tid >> 1;
    const int ha = tid & 1;
    int gm = mtile * BM + rA;
    int gmc = gm < cnt ? gm : cnt - 1;
    const int arow = idxE[gmc];
    const float*  a_f = (const float*)Av  + (size_t)arow * lda + 8 * ha;
    const __half* a_h = (const __half*)Av + (size_t)arow * lda + 8 * ha;
    const uint32_t a_sts = s_u32 + (uint32_t)((rA * SAS + 8 * ha) * 2);

    // ---- B loader: k-row kB = tid>>4, n-chunk (tid&15)*8, 8 floats -> STS.128
    const int kB = tid >> 4;
    const int nch = (tid & 15) * 8;
    const float* b_src = We + (size_t)kB * N + n0 + nch;
    const uint32_t b_sts = s_u32 + (uint32_t)((SA_H + kB * SBS + nch) * 2);

    const int KT = K / BK;
    uint32_t bufA[4], bufB[4];

    auto load_g = [&](int t) {
        // A
        if (A_HALF) {
            uint4 v = *reinterpret_cast<const uint4*>(a_h + (size_t)t * BK);
            bufA[0] = v.x; bufA[1] = v.y; bufA[2] = v.z; bufA[3] = v.w;
        } else {
            float4 v0 = *reinterpret_cast<const float4*>(a_f + (size_t)t * BK);
            float4 v1 = *reinterpret_cast<const float4*>(a_f + (size_t)t * BK + 4);
            bufA[0] = pack2(v0.x, v0.y); bufA[1] = pack2(v0.z, v0.w);
            bufA[2] = pack2(v1.x, v1.y); bufA[3] = pack2(v1.z, v1.w);
        }
        // B
        const float* bs = b_src + (size_t)t * BK * N;
        if (ALIGN16) {
            float4 v0 = *reinterpret_cast<const float4*>(bs);
            float4 v1 = *reinterpret_cast<const float4*>(bs + 4);
            bufB[0] = pack2(v0.x, v0.y); bufB[1] = pack2(v0.z, v0.w);
            bufB[2] = pack2(v1.x, v1.y); bufB[3] = pack2(v1.z, v1.w);
        } else {
#pragma unroll
            for (int j = 0; j < 4; j++) {
                int gn = n0 + nch + 2 * j;
                if (gn < N) {
                    float2 v = *reinterpret_cast<const float2*>(bs + 2 * j);
                    bufB[j] = pack2(v.x, v.y);
                } else {
                    bufB[j] = 0u;
                }
            }
        }
    };
    auto do_sts = [&](int stage) {
        const uint32_t off = (uint32_t)(stage * STAGE_H * 2);
        sts128(a_sts + off, bufA);
        sts128(b_sts + off, bufB);
    };

    // warp tiling: 2 warps along M (64), 4 along N (32)
    const int wm = (warp & 1) * 64;
    const int wn = (warp >> 1) * 32;
    const int g  = lane >> 2;
    const int tg = lane & 3;

    // ldmatrix source addresses (per-warp, stage-relative)
    const int a_ld_row = wm + (lane & 15);
    const int a_ld_col = (lane >> 4) * 8;
    const uint32_t a_ld = s_u32 + (uint32_t)((a_ld_row * SAS + a_ld_col) * 2);
    const int b_ld_k = lane & 15;
    const int b_ld_n = wn + (lane >> 4) * 8;
    const uint32_t b_ld = s_u32 + (uint32_t)((SA_H + b_ld_k * SBS + b_ld_n) * 2);

    float acc[4][4][4];
#pragma unroll
    for (int mi = 0; mi < 4; mi++)
#pragma unroll
        for (int ni = 0; ni < 4; ni++)
#pragma unroll
            for (int k = 0; k < 4; k++) acc[mi][ni][k] = 0.f;

    load_g(0);
    do_sts(0);

    for (int t = 0; t < KT; t++) {
        __syncthreads();
        if (t + 1 < KT) load_g(t + 1);

        const uint32_t soff = (uint32_t)((t & 1) * STAGE_H * 2);
        uint32_t bf[8];
        ldsm4t(bf,     b_ld + soff);            // ni 0,1 (n..n+15)
        ldsm4t(bf + 4, b_ld + soff + 32);       // ni 2,3 (n+16..n+31)
#pragma unroll
        for (int mi = 0; mi < 4; mi++) {
            uint32_t af[4];
            ldsm4(af, a_ld + soff + (uint32_t)(mi * 16 * SAS * 2));
            // bf tile order per ldsm4t: [k0-7,n][k8-15,n][k0-7,n+8][k8-15,n+8]
            mma_f16(acc[mi][0], af, bf[0], bf[1]);
            mma_f16(acc[mi][1], af, bf[2], bf[3]);
            mma_f16(acc[mi][2], af, bf[4], bf[5]);
            mma_f16(acc[mi][3], af, bf[6], bf[7]);
        }

        if (t + 1 < KT) do_sts((t + 1) & 1);
    }

    // ---- epilogue: bias (+gelu), scatter to original sample rows ----
#pragma unroll
    for (int mi = 0; mi < 4; mi++) {
#pragma unroll
        for (int half = 0; half < 2; half++) {
            const int m = wm + mi * 16 + g + half * 8;
            const int gmm = mtile * BM + m;
            if (gmm >= cnt) continue;
            const int orow = idxE[gmm];
#pragma unroll
            for (int ni = 0; ni < 4; ni++) {
                const int gn = n0 + wn + ni * 8 + tg * 2;
                float v0 = acc[mi][ni][half * 2 + 0];
                float v1 = acc[mi][ni][half * 2 + 1];
                if (OUT_HALF) {
                    // L1/L2: N multiple of 128, no bounds needed
                    float r0 = v0 + be[gn];
                    float r1 = v1 + be[gn + 1];
                    if (DO_GELU) { r0 = gelu_exact(r0); r1 = gelu_exact(r1); }
                    __half2 hv = __float22half2_rn(make_float2(r0, r1));
                    *reinterpret_cast<__half2*>((__half*)Coutv + (size_t)orow * ldc + gn) = hv;
                } else {
                    float* op = (float*)Coutv + (size_t)orow * ldc;
                    if (gn + 1 < N) {
                        float r0 = v0 + be[gn];
                        float r1 = v1 + be[gn + 1];
                        if (DO_GELU) { r0 = gelu_exact(r0); r1 = gelu_exact(r1); }
                        *reinterpret_cast<float2*>(op + gn) = make_float2(r0, r1);
                    } else if (gn < N) {
                        float r0 = v0 + be[gn];
                        if (DO_GELU) r0 = gelu_exact(r0);
                        op[gn] = r0;
                    }
                }
            }
        }
    }
}

// ---------------------------------------------------------------------------
__global__ void logsoftmax_kernel(float* __restrict__ out) {
    const int b = blockIdx.x;
    float* row = out + (size_t)b * C_;
    __shared__ float sred[256];
    const int tid = threadIdx.x;

    float lmax = -3.4e38f;
    for (int i = tid; i < C_; i += 256) lmax = fmaxf(lmax, row[i]);
    sred[tid] = lmax;
    __syncthreads();
    for (int s = 128; s > 0; s >>= 1) {
        if (tid < s) sred[tid] = fmaxf(sred[tid], sred[tid + s]);
        __syncthreads();
    }
    const float mx = sred[0];
    __syncthreads();

    float lsum = 0.f;
    for (int i = tid; i < C_; i += 256) lsum += expf(row[i] - mx);
    sred[tid] = lsum;
    __syncthreads();
    for (int s = 128; s > 0; s >>= 1) {
        if (tid < s) sred[tid] += sred[tid + s];
        __syncthreads();
    }
    const float lse = mx + logf(sred[0]);

    for (int i = tid; i < C_; i += 256) row[i] = row[i] - lse;
}

// ---------------------------------------------------------------------------
extern "C" void kernel_launch(void* const* d_in, const int* in_sizes, int n_in,
                              void* d_out, int out_size)
{
    const float* x  = (const float*)d_in[0];
    const float* mf = (const float*)d_in[1];
    const float* W1 = (const float*)d_in[2];
    const float* b1 = (const float*)d_in[3];
    const float* W2 = (const float*)d_in[4];
    const float* b2 = (const float*)d_in[5];
    const float* W3 = (const float*)d_in[6];
    const float* b3 = (const float*)d_in[7];
    float* out = (float*)d_out;

    void *h1p = nullptr, *h2p = nullptr;
    cudaGetSymbolAddress(&h1p, g_h1);
    cudaGetSymbolAddress(&h2p, g_h2);

    route_kernel<<<1, B_>>>(mf);

    // L1: x fp32 [cnt,1536] @ W1 -> gelu -> h1 (fp16)
    expert_gemm<true, false, true, true>
        <<<dim3(H_ / BN, MT, E_), NTHREADS>>>(x, D_, W1, b1, h1p, H_, D_, H_);
    // L2: h1 fp16 [cnt,3072] @ W2 -> gelu -> h2 (fp16)
    expert_gemm<true, true, true, true>
        <<<dim3(H_ / BN, MT, E_), NTHREADS>>>(h1p, H_, W2, b2, h2p, H_, H_, H_);
    // L3: h2 fp16 [cnt,3072] @ W3 + b3 -> preds (fp32, 8B-aligned rows)
    expert_gemm<false, true, false, false>
        <<<dim3((C_ + BN - 1) / BN, MT, E_), NTHREADS>>>(h2p, H_, W3, b3, out, C_, H_, C_);
    logsoftmax_kernel<<<B_, 256>>>(out);
}